// round 7
// baseline (speedup 1.0000x reference)
#include <cuda_runtime.h>
#include <cuda_bf16.h>
#include <cstdint>

#define HH 192
#define WW 192
#define NPIX (HH * WW)      // 36864
#define CIN 128
#define NHEAD 8
#define KST 256             // [hi(128) | lo(128)] storage; 3 split terms via k remap

// Scratch
__device__ float g_v[256 * NPIX];            // v projection
__device__ float g_s0[NHEAD * NPIX];         // per-head q.k / 16
__device__ __nv_bfloat16 g_wbf[768 * KST];   // rows 0-511: per-head [q(32)|k(32)]; 512-767: v
__device__ __nv_bfloat16 g_xt[NPIX * KST];   // x transposed, [p][hi|lo]

// ---------------------------------------------------------------------------
// Helpers (base compute_103 features only: cp.async, ldmatrix, mma.sync)
// ---------------------------------------------------------------------------
__device__ __forceinline__ uint32_t smem_u32(const void* p) {
    uint32_t a;
    asm("{ .reg .u64 t; cvta.to.shared.u64 t, %1; cvt.u32.u64 %0, t; }" : "=r"(a) : "l"(p));
    return a;
}
__device__ __forceinline__ void cp16(uint32_t saddr, const void* g) {
    asm volatile("cp.async.cg.shared.global [%0], [%1], 16;\n" :: "r"(saddr), "l"(g));
}
__device__ __forceinline__ void ldsm_x4(uint32_t* r, uint32_t addr) {
    asm volatile("ldmatrix.sync.aligned.m8n8.x4.shared.b16 {%0,%1,%2,%3}, [%4];"
                 : "=r"(r[0]), "=r"(r[1]), "=r"(r[2]), "=r"(r[3]) : "r"(addr));
}
__device__ __forceinline__ void mma16816(float* d, const uint32_t* a, const uint32_t* b) {
    asm volatile(
        "mma.sync.aligned.m16n8k16.row.col.f32.bf16.bf16.f32 "
        "{%0,%1,%2,%3}, {%4,%5,%6,%7}, {%8,%9}, {%0,%1,%2,%3};"
        : "+f"(d[0]), "+f"(d[1]), "+f"(d[2]), "+f"(d[3])
        : "r"(a[0]), "r"(a[1]), "r"(a[2]), "r"(a[3]), "r"(b[0]), "r"(b[1]));
}

// Split-term k offsets per 32-wide K chunk kt in [0,12):
//   kt 0-3: hi.hi   kt 4-7: lo.hi   kt 8-11: hi.lo
__device__ __forceinline__ int kOffA(int kt) {
    return (kt < 4) ? kt * 32 : (kt < 8) ? 128 + (kt - 4) * 32 : (kt - 8) * 32;
}
__device__ __forceinline__ int kOffB(int kt) {
    return (kt < 4) ? kt * 32 : (kt < 8) ? (kt - 4) * 32 : 128 + (kt - 8) * 32;
}

// ---------------------------------------------------------------------------
// Precompute 1: split weights -> g_wbf [768][256] = [hi | lo]
// ---------------------------------------------------------------------------
__global__ void __launch_bounds__(128) wbf_kernel(
    const float* __restrict__ wq, const float* __restrict__ wk,
    const float* __restrict__ wv)
{
    const int r = blockIdx.x, c = threadIdx.x;
    const float* src;
    if (r < 512) {
        const int h = r >> 6, j = r & 63;
        src = (j < 32) ? wq + (h * 32 + j) * CIN
                       : wk + (h * 32 + j - 32) * CIN;
    } else {
        src = wv + (r - 512) * CIN;
    }
    const float a = src[c];
    const __nv_bfloat16 hi = __float2bfloat16(a);
    const __nv_bfloat16 lo = __float2bfloat16(a - __bfloat162float(hi));
    g_wbf[r * KST + c]       = hi;
    g_wbf[r * KST + 128 + c] = lo;
}

// ---------------------------------------------------------------------------
// Precompute 2: transpose + split x -> g_xt [36864][256] = [hi | lo]
// ---------------------------------------------------------------------------
__global__ void __launch_bounds__(256) xt_kernel(const float* __restrict__ x)
{
    __shared__ float tile[32][33];
    const int tx = threadIdx.x & 31, ty = threadIdx.x >> 5;
    const int p0 = blockIdx.x * 32, c0 = blockIdx.y * 32;
#pragma unroll
    for (int d = 0; d < 4; d++)
        tile[ty * 4 + d][tx] = x[(c0 + ty * 4 + d) * NPIX + p0 + tx];
    __syncthreads();
#pragma unroll
    for (int d = 0; d < 4; d++) {
        const int p = p0 + ty * 4 + d;
        const float a = tile[tx][ty * 4 + d];
        const __nv_bfloat16 hi = __float2bfloat16(a);
        const __nv_bfloat16 lo = __float2bfloat16(a - __bfloat162float(hi));
        g_xt[(size_t)p * KST + c0 + tx]       = hi;
        g_xt[(size_t)p * KST + 128 + c0 + tx] = lo;
    }
}

// ---------------------------------------------------------------------------
// Kernel A: HMMA GEMM, CTA 128x128, BK=32, 3-stage cp.async, 8 warps (2m x 4n).
// by 0-3: q/k tiles -> fused s0 epilogue. by 4-5: v tiles -> g_v.
// ---------------------------------------------------------------------------
#define ASTRB 80
#define STG_BYTES (128 * ASTRB)
#define SMEM_GEMM (6 * STG_BYTES)     // 61440 B

__global__ void __launch_bounds__(256, 2) qkv_mma_kernel()
{
    extern __shared__ __align__(128) char smem[];
    const uint32_t sbase = smem_u32(smem);
    const int t = threadIdx.x, lane = t & 31, w = t >> 5;
    const int wm = w >> 2, wn = w & 3;
    const int by = blockIdx.y;
    const int m0 = by * 128;
    const int n0 = blockIdx.x * 128;

    const __nv_bfloat16* Ag = g_wbf + (size_t)m0 * KST;
    const __nv_bfloat16* Bg = g_xt  + (size_t)n0 * KST;

    const int r0c = t >> 2, c0c = t & 3;
    const int r1c = r0c + 64;

    auto issue_copy = [&](int kt) {
        const int s = kt % 3;
        const int ka = kOffA(kt), kb = kOffB(kt);
        const uint32_t sA = sbase + s * STG_BYTES;
        const uint32_t sB = sbase + 3 * STG_BYTES + s * STG_BYTES;
        cp16(sA + r0c * ASTRB + c0c * 16, Ag + (size_t)r0c * KST + ka + c0c * 8);
        cp16(sB + r0c * ASTRB + c0c * 16, Bg + (size_t)r0c * KST + kb + c0c * 8);
        cp16(sA + r1c * ASTRB + c0c * 16, Ag + (size_t)r1c * KST + ka + c0c * 8);
        cp16(sB + r1c * ASTRB + c0c * 16, Bg + (size_t)r1c * KST + kb + c0c * 8);
        asm volatile("cp.async.commit_group;\n");
    };

    issue_copy(0);
    issue_copy(1);

    float acc[4][4][4];
#pragma unroll
    for (int i = 0; i < 4; i++)
#pragma unroll
        for (int j = 0; j < 4; j++)
#pragma unroll
            for (int e = 0; e < 4; e++) acc[i][j][e] = 0.f;

    const uint32_t aRow = (uint32_t)(wm * 64 + (lane & 15));
    const uint32_t aChunkLane = (uint32_t)(lane >> 4);
    const int bsel = lane >> 3, br = lane & 7;
    const uint32_t bRowBase = (uint32_t)(wn * 32 + ((bsel >> 1) << 3) + br);
    const uint32_t bChunkLane = (uint32_t)(bsel & 1);

#pragma unroll 1
    for (int kt = 0; kt < 12; kt++) {
        if (kt < 11) asm volatile("cp.async.wait_group 1;\n" ::: "memory");
        else         asm volatile("cp.async.wait_group 0;\n" ::: "memory");
        __syncthreads();
        if (kt + 2 < 12) issue_copy(kt + 2);

        const int s = kt % 3;
        const uint32_t sA = sbase + s * STG_BYTES;
        const uint32_t sB = sbase + 3 * STG_BYTES + s * STG_BYTES;

#pragma unroll
        for (int ks = 0; ks < 2; ks++) {
            uint32_t afr[4][4];
#pragma unroll
            for (int mi = 0; mi < 4; mi++)
                ldsm_x4(afr[mi], sA + (aRow + mi * 16) * ASTRB
                                    + (ks * 2 + aChunkLane) * 16);
            uint32_t bfr[4][2];
#pragma unroll
            for (int ni2 = 0; ni2 < 2; ni2++) {
                uint32_t rr[4];
                ldsm_x4(rr, sB + (bRowBase + ni2 * 16) * ASTRB
                               + (ks * 2 + bChunkLane) * 16);
                bfr[ni2 * 2 + 0][0] = rr[0]; bfr[ni2 * 2 + 0][1] = rr[1];
                bfr[ni2 * 2 + 1][0] = rr[2]; bfr[ni2 * 2 + 1][1] = rr[3];
            }
#pragma unroll
            for (int mi = 0; mi < 4; mi++)
#pragma unroll
                for (int nj = 0; nj < 4; nj++)
                    mma16816(acc[mi][nj], afr[mi], bfr[nj]);
        }
        __syncthreads();
    }

    if (by < 4) {
        const int head = 2 * by + wm;
        float part[4][2];
#pragma unroll
        for (int nj = 0; nj < 4; nj++)
#pragma unroll
            for (int pe = 0; pe < 2; pe++)
                part[nj][pe] = acc[0][nj][pe]     * acc[2][nj][pe]
                             + acc[1][nj][pe]     * acc[3][nj][pe]
                             + acc[0][nj][pe + 2] * acc[2][nj][pe + 2]
                             + acc[1][nj][pe + 2] * acc[3][nj][pe + 2];
#pragma unroll
        for (int d = 4; d <= 16; d <<= 1)
#pragma unroll
            for (int nj = 0; nj < 4; nj++)
#pragma unroll
                for (int pe = 0; pe < 2; pe++)
                    part[nj][pe] += __shfl_xor_sync(0xffffffffu, part[nj][pe], d);
        if ((lane >> 2) == 0) {
            float* dst = g_s0 + (size_t)head * NPIX + n0 + wn * 32 + (lane & 3) * 2;
#pragma unroll
            for (int nj = 0; nj < 4; nj++) {
                dst[nj * 8]     = part[nj][0] * 0.0625f;
                dst[nj * 8 + 1] = part[nj][1] * 0.0625f;
            }
        }
    } else {
        const int mBase = (by - 4) * 128 + wm * 64 + (lane >> 2);
        const int pBase = n0 + wn * 32 + (lane & 3) * 2;
#pragma unroll
        for (int mi = 0; mi < 4; mi++) {
#pragma unroll
            for (int nj = 0; nj < 4; nj++) {
                const size_t i0 = (size_t)(mBase + mi * 16) * NPIX + pBase + nj * 8;
                const size_t i1 = i0 + 8 * NPIX;
                *(float2*)&g_v[i0] = make_float2(acc[mi][nj][0], acc[mi][nj][1]);
                *(float2*)&g_v[i1] = make_float2(acc[mi][nj][2], acc[mi][nj][3]);
            }
        }
    }
}

// ---------------------------------------------------------------------------
// Kernel C: per-pixel softmax over 9 shifted s0 (OOB -> logit 0), then a
// shuffle-based 9-tap combine: 3 coalesced row loads/channel + shfl neighbors.
// ---------------------------------------------------------------------------
__global__ void __launch_bounds__(256) attn_kernel(float* __restrict__ out)
{
    __shared__ float wsm[NHEAD * 9 * 32];
    const int t = threadIdx.x;
    const int h = blockIdx.y;
    const int w0 = blockIdx.x * 32;

    // Phase 1: softmax weights for 32 pixels x 8 heads
    {
        const int pix = t & 31, head = t >> 5;
        const int w = w0 + pix;
        float lg[9];
#pragma unroll
        for (int s = 0; s < 9; s++) {
            const int hh = h + s / 3 - 1;
            const int ww = w + s % 3 - 1;
            const bool ok = ((unsigned)hh < HH) && ((unsigned)ww < WW);
            lg[s] = ok ? g_s0[head * NPIX + hh * WW + ww] : 0.0f;
        }
        float mx = lg[0];
#pragma unroll
        for (int s = 1; s < 9; s++) mx = fmaxf(mx, lg[s]);
        float e[9], sum = 0.f;
#pragma unroll
        for (int s = 0; s < 9; s++) { e[s] = __expf(lg[s] - mx); sum += e[s]; }
        const float inv = 1.0f / sum;
#pragma unroll
        for (int s = 0; s < 9; s++)
            wsm[(head * 9 + s) * 32 + pix] = e[s] * inv;
    }
    __syncthreads();

    // Phase 2: warp = head, lane = pixel. Per channel: 3 coalesced row loads,
    // neighbors via shfl; lanes 0/31 patch edges with predicated loads.
    const int lane = t & 31, head = t >> 5;
    const int w = w0 + lane;
    float wr[9];
#pragma unroll
    for (int s = 0; s < 9; s++) {
        const int hh = h + s / 3 - 1;
        const int ww = w + s % 3 - 1;
        const bool ok = ((unsigned)hh < HH) && ((unsigned)ww < WW);
        wr[s] = ok ? wsm[(head * 9 + s) * 32 + lane] : 0.0f;
    }
    const int row[3] = { max(h - 1, 0) * WW, h * WW, min(h + 1, HH - 1) * WW };
    const int wl  = max(w0 - 1, 0);          // left edge pixel (weight 0 if OOB)
    const int wrt = min(w0 + 32, WW - 1);    // right edge pixel

    const float* vbase = g_v + (size_t)(head * 32) * NPIX;
    float* obase = out + (size_t)(head * 32) * NPIX + h * WW + w;

#pragma unroll 4
    for (int j = 0; j < 32; j++) {
        const float* vp = vbase + (size_t)j * NPIX;
        float acc = 0.f;
#pragma unroll
        for (int r = 0; r < 3; r++) {
            const float c = vp[row[r] + w];
            float l = __shfl_up_sync(0xffffffffu, c, 1);
            float rt = __shfl_down_sync(0xffffffffu, c, 1);
            if (lane == 0)  l  = vp[row[r] + wl];
            if (lane == 31) rt = vp[row[r] + wrt];
            acc = fmaf(wr[3 * r], l, acc);
            acc = fmaf(wr[3 * r + 1], c, acc);
            acc = fmaf(wr[3 * r + 2], rt, acc);
        }
        obase[(size_t)j * NPIX] = acc;
    }
}

// ---------------------------------------------------------------------------
extern "C" void kernel_launch(void* const* d_in, const int* in_sizes, int n_in,
                              void* d_out, int out_size)
{
    const float* x  = (const float*)d_in[0];
    const float* wq = (const float*)d_in[1];
    const float* wk = (const float*)d_in[2];
    const float* wv = (const float*)d_in[3];
    float* out = (float*)d_out;

    cudaFuncSetAttribute(qkv_mma_kernel,
                         cudaFuncAttributeMaxDynamicSharedMemorySize, SMEM_GEMM);

    wbf_kernel<<<768, 128>>>(wq, wk, wv);
    xt_kernel<<<dim3(NPIX / 32, 4), 256>>>(x);
    qkv_mma_kernel<<<dim3(288, 6), 256, SMEM_GEMM>>>();
    attn_kernel<<<dim3(WW / 32, HH), 256>>>(out);
}

// round 9
// speedup vs baseline: 1.5535x; 1.5535x over previous
#include <cuda_runtime.h>
#include <cuda_bf16.h>
#include <cstdint>

#define HH 192
#define WW 192
#define NPIX (HH * WW)      // 36864
#define CIN 128
#define NHEAD 8
#define KST 256             // [hi(128) | lo(128)] storage; 3 split terms via k remap

// Scratch
__device__ float g_vt[NPIX * 256];           // v projection, PIXEL-major [p][c]
__device__ float g_s0[NHEAD * NPIX];         // per-head q.k / 16
__device__ __nv_bfloat16 g_wbf[768 * KST];   // rows 0-511: per-head [q(32)|k(32)]; 512-767: v
__device__ __nv_bfloat16 g_xt[NPIX * KST];   // x transposed, [p][hi|lo]

// ---------------------------------------------------------------------------
// Helpers (base compute_103 features only: cp.async, ldmatrix, mma.sync)
// ---------------------------------------------------------------------------
__device__ __forceinline__ uint32_t smem_u32(const void* p) {
    uint32_t a;
    asm("{ .reg .u64 t; cvta.to.shared.u64 t, %1; cvt.u32.u64 %0, t; }" : "=r"(a) : "l"(p));
    return a;
}
__device__ __forceinline__ void cp16(uint32_t saddr, const void* g) {
    asm volatile("cp.async.cg.shared.global [%0], [%1], 16;\n" :: "r"(saddr), "l"(g));
}
__device__ __forceinline__ void ldsm_x4(uint32_t* r, uint32_t addr) {
    asm volatile("ldmatrix.sync.aligned.m8n8.x4.shared.b16 {%0,%1,%2,%3}, [%4];"
                 : "=r"(r[0]), "=r"(r[1]), "=r"(r[2]), "=r"(r[3]) : "r"(addr));
}
__device__ __forceinline__ void mma16816(float* d, const uint32_t* a, const uint32_t* b) {
    asm volatile(
        "mma.sync.aligned.m16n8k16.row.col.f32.bf16.bf16.f32 "
        "{%0,%1,%2,%3}, {%4,%5,%6,%7}, {%8,%9}, {%0,%1,%2,%3};"
        : "+f"(d[0]), "+f"(d[1]), "+f"(d[2]), "+f"(d[3])
        : "r"(a[0]), "r"(a[1]), "r"(a[2]), "r"(a[3]), "r"(b[0]), "r"(b[1]));
}

// Split-term k offsets per 32-wide K chunk kt in [0,12):
//   kt 0-3: hi.hi   kt 4-7: lo.hi   kt 8-11: hi.lo
__device__ __forceinline__ int kOffA(int kt) {
    return (kt < 4) ? kt * 32 : (kt < 8) ? 128 + (kt - 4) * 32 : (kt - 8) * 32;
}
__device__ __forceinline__ int kOffB(int kt) {
    return (kt < 4) ? kt * 32 : (kt < 8) ? (kt - 4) * 32 : 128 + (kt - 8) * 32;
}

// ---------------------------------------------------------------------------
// Precompute 1: split weights -> g_wbf [768][256] = [hi | lo]
// ---------------------------------------------------------------------------
__global__ void __launch_bounds__(128) wbf_kernel(
    const float* __restrict__ wq, const float* __restrict__ wk,
    const float* __restrict__ wv)
{
    const int r = blockIdx.x, c = threadIdx.x;
    const float* src;
    if (r < 512) {
        const int h = r >> 6, j = r & 63;
        src = (j < 32) ? wq + (h * 32 + j) * CIN
                       : wk + (h * 32 + j - 32) * CIN;
    } else {
        src = wv + (r - 512) * CIN;
    }
    const float a = src[c];
    const __nv_bfloat16 hi = __float2bfloat16(a);
    const __nv_bfloat16 lo = __float2bfloat16(a - __bfloat162float(hi));
    g_wbf[r * KST + c]       = hi;
    g_wbf[r * KST + 128 + c] = lo;
}

// ---------------------------------------------------------------------------
// Precompute 2: transpose + split x -> g_xt [36864][256] = [hi | lo]
// ---------------------------------------------------------------------------
__global__ void __launch_bounds__(256) xt_kernel(const float* __restrict__ x)
{
    __shared__ float tile[32][33];
    const int tx = threadIdx.x & 31, ty = threadIdx.x >> 5;
    const int p0 = blockIdx.x * 32, c0 = blockIdx.y * 32;
#pragma unroll
    for (int d = 0; d < 4; d++)
        tile[ty * 4 + d][tx] = x[(c0 + ty * 4 + d) * NPIX + p0 + tx];
    __syncthreads();
#pragma unroll
    for (int d = 0; d < 4; d++) {
        const int p = p0 + ty * 4 + d;
        const float a = tile[tx][ty * 4 + d];
        const __nv_bfloat16 hi = __float2bfloat16(a);
        const __nv_bfloat16 lo = __float2bfloat16(a - __bfloat162float(hi));
        g_xt[(size_t)p * KST + c0 + tx]       = hi;
        g_xt[(size_t)p * KST + 128 + c0 + tx] = lo;
    }
}

// ---------------------------------------------------------------------------
// Kernel A: HMMA GEMM, CTA 128x128, BK=32, 3-stage cp.async, 8 warps (2m x 4n).
// by 0-3: q/k tiles -> fused s0 epilogue. by 4-5: v tiles -> g_vt (pixel-major).
// ---------------------------------------------------------------------------
#define ASTRB 80
#define STG_BYTES (128 * ASTRB)
#define SMEM_GEMM (6 * STG_BYTES)     // 61440 B

__global__ void __launch_bounds__(256, 2) qkv_mma_kernel()
{
    extern __shared__ __align__(128) char smem[];
    const uint32_t sbase = smem_u32(smem);
    const int t = threadIdx.x, lane = t & 31, w = t >> 5;
    const int wm = w >> 2, wn = w & 3;
    const int by = blockIdx.y;
    const int m0 = by * 128;
    const int n0 = blockIdx.x * 128;

    const __nv_bfloat16* Ag = g_wbf + (size_t)m0 * KST;
    const __nv_bfloat16* Bg = g_xt  + (size_t)n0 * KST;

    const int r0c = t >> 2, c0c = t & 3;
    const int r1c = r0c + 64;

    auto issue_copy = [&](int kt) {
        const int s = kt % 3;
        const int ka = kOffA(kt), kb = kOffB(kt);
        const uint32_t sA = sbase + s * STG_BYTES;
        const uint32_t sB = sbase + 3 * STG_BYTES + s * STG_BYTES;
        cp16(sA + r0c * ASTRB + c0c * 16, Ag + (size_t)r0c * KST + ka + c0c * 8);
        cp16(sB + r0c * ASTRB + c0c * 16, Bg + (size_t)r0c * KST + kb + c0c * 8);
        cp16(sA + r1c * ASTRB + c0c * 16, Ag + (size_t)r1c * KST + ka + c0c * 8);
        cp16(sB + r1c * ASTRB + c0c * 16, Bg + (size_t)r1c * KST + kb + c0c * 8);
        asm volatile("cp.async.commit_group;\n");
    };

    issue_copy(0);
    issue_copy(1);

    float acc[4][4][4];
#pragma unroll
    for (int i = 0; i < 4; i++)
#pragma unroll
        for (int j = 0; j < 4; j++)
#pragma unroll
            for (int e = 0; e < 4; e++) acc[i][j][e] = 0.f;

    const uint32_t aRow = (uint32_t)(wm * 64 + (lane & 15));
    const uint32_t aChunkLane = (uint32_t)(lane >> 4);
    const int bsel = lane >> 3, br = lane & 7;
    const uint32_t bRowBase = (uint32_t)(wn * 32 + ((bsel >> 1) << 3) + br);
    const uint32_t bChunkLane = (uint32_t)(bsel & 1);

#pragma unroll 1
    for (int kt = 0; kt < 12; kt++) {
        if (kt < 11) asm volatile("cp.async.wait_group 1;\n" ::: "memory");
        else         asm volatile("cp.async.wait_group 0;\n" ::: "memory");
        __syncthreads();
        if (kt + 2 < 12) issue_copy(kt + 2);

        const int s = kt % 3;
        const uint32_t sA = sbase + s * STG_BYTES;
        const uint32_t sB = sbase + 3 * STG_BYTES + s * STG_BYTES;

#pragma unroll
        for (int ks = 0; ks < 2; ks++) {
            uint32_t afr[4][4];
#pragma unroll
            for (int mi = 0; mi < 4; mi++)
                ldsm_x4(afr[mi], sA + (aRow + mi * 16) * ASTRB
                                    + (ks * 2 + aChunkLane) * 16);
            uint32_t bfr[4][2];
#pragma unroll
            for (int ni2 = 0; ni2 < 2; ni2++) {
                uint32_t rr[4];
                ldsm_x4(rr, sB + (bRowBase + ni2 * 16) * ASTRB
                               + (ks * 2 + bChunkLane) * 16);
                bfr[ni2 * 2 + 0][0] = rr[0]; bfr[ni2 * 2 + 0][1] = rr[1];
                bfr[ni2 * 2 + 1][0] = rr[2]; bfr[ni2 * 2 + 1][1] = rr[3];
            }
#pragma unroll
            for (int mi = 0; mi < 4; mi++)
#pragma unroll
                for (int nj = 0; nj < 4; nj++)
                    mma16816(acc[mi][nj], afr[mi], bfr[nj]);
        }
        __syncthreads();
    }

    if (by < 4) {
        const int head = 2 * by + wm;
        float part[4][2];
#pragma unroll
        for (int nj = 0; nj < 4; nj++)
#pragma unroll
            for (int pe = 0; pe < 2; pe++)
                part[nj][pe] = acc[0][nj][pe]     * acc[2][nj][pe]
                             + acc[1][nj][pe]     * acc[3][nj][pe]
                             + acc[0][nj][pe + 2] * acc[2][nj][pe + 2]
                             + acc[1][nj][pe + 2] * acc[3][nj][pe + 2];
#pragma unroll
        for (int d = 4; d <= 16; d <<= 1)
#pragma unroll
            for (int nj = 0; nj < 4; nj++)
#pragma unroll
                for (int pe = 0; pe < 2; pe++)
                    part[nj][pe] += __shfl_xor_sync(0xffffffffu, part[nj][pe], d);
        if ((lane >> 2) == 0) {
            float* dst = g_s0 + (size_t)head * NPIX + n0 + wn * 32 + (lane & 3) * 2;
#pragma unroll
            for (int nj = 0; nj < 4; nj++) {
                dst[nj * 8]     = part[nj][0] * 0.0625f;
                dst[nj * 8 + 1] = part[nj][1] * 0.0625f;
            }
        }
    } else {
        // v epilogue: transposed (pixel-major) scatter stores into g_vt[p][c]
        const int cBase = (by - 4) * 128 + wm * 64 + (lane >> 2);
        const int pBase = n0 + wn * 32 + (lane & 3) * 2;
#pragma unroll
        for (int mi = 0; mi < 4; mi++) {
#pragma unroll
            for (int nj = 0; nj < 4; nj++) {
                const int cc = cBase + mi * 16;
                const int pp = pBase + nj * 8;
                g_vt[(size_t)pp * 256 + cc]           = acc[mi][nj][0];
                g_vt[(size_t)(pp + 1) * 256 + cc]     = acc[mi][nj][1];
                g_vt[(size_t)pp * 256 + cc + 8]       = acc[mi][nj][2];
                g_vt[(size_t)(pp + 1) * 256 + cc + 8] = acc[mi][nj][3];
            }
        }
    }
}

// ---------------------------------------------------------------------------
// Kernel C: softmax over 9 shifted s0 (OOB slot -> logit 0 in the softmax,
// weight 0 for the value product), then sliding-window 9-tap combine on
// pixel-major v: thread = channel, 3 coalesced loads per pixel step.
// ---------------------------------------------------------------------------
__global__ void __launch_bounds__(256) attn_kernel(float* __restrict__ out)
{
    __shared__ float wsm[NHEAD * 9 * 32];      // [head][slot][pix], OOB -> 0
    __shared__ float swo[NHEAD][32][33];       // warp-local out transpose
    const int t = threadIdx.x;
    const int h = blockIdx.y;
    const int w0 = blockIdx.x * 32;
    const int lane = t & 31, head = t >> 5;

    // Phase 1: softmax weights for this head's 32 pixels (warp-local).
    // OOB slots keep logit 0 inside the softmax sum but get weight 0 stored.
    {
        const int w = w0 + lane;
        float lg[9];
        bool okm[9];
#pragma unroll
        for (int s = 0; s < 9; s++) {
            const int hh = h + s / 3 - 1;
            const int ww = w + s % 3 - 1;
            okm[s] = ((unsigned)hh < HH) && ((unsigned)ww < WW);
            lg[s] = okm[s] ? g_s0[head * NPIX + hh * WW + ww] : 0.0f;
        }
        float mx = lg[0];
#pragma unroll
        for (int s = 1; s < 9; s++) mx = fmaxf(mx, lg[s]);
        float e[9], sum = 0.f;
#pragma unroll
        for (int s = 0; s < 9; s++) { e[s] = __expf(lg[s] - mx); sum += e[s]; }
        const float inv = 1.0f / sum;
#pragma unroll
        for (int s = 0; s < 9; s++)
            wsm[(head * 9 + s) * 32 + lane] = okm[s] ? e[s] * inv : 0.0f;
    }
    __syncwarp();

    // Phase 2: thread = channel t; slide 3x3 window along the 32-pixel row.
    // Clamped loads are safe: their weights are 0.
    const int c = t;
    const int r0 = max(h - 1, 0) * WW;
    const int r1 = h * WW;
    const int r2 = min(h + 1, HH - 1) * WW;
    const float* wp = &wsm[head * 9 * 32];

    const int wl = max(w0 - 1, 0);
    float P0 = __ldg(&g_vt[(size_t)(r0 + wl) * 256 + c]);
    float P1 = __ldg(&g_vt[(size_t)(r1 + wl) * 256 + c]);
    float P2 = __ldg(&g_vt[(size_t)(r2 + wl) * 256 + c]);
    float C0 = __ldg(&g_vt[(size_t)(r0 + w0) * 256 + c]);
    float C1 = __ldg(&g_vt[(size_t)(r1 + w0) * 256 + c]);
    float C2 = __ldg(&g_vt[(size_t)(r2 + w0) * 256 + c]);

#pragma unroll 4
    for (int i = 0; i < 32; i++) {
        const int wn_ = min(w0 + i + 1, WW - 1);
        const float N0 = __ldg(&g_vt[(size_t)(r0 + wn_) * 256 + c]);
        const float N1 = __ldg(&g_vt[(size_t)(r1 + wn_) * 256 + c]);
        const float N2 = __ldg(&g_vt[(size_t)(r2 + wn_) * 256 + c]);
        float a;
        a = wp[0 * 32 + i] * P0;
        a = fmaf(wp[1 * 32 + i], C0, a);
        a = fmaf(wp[2 * 32 + i], N0, a);
        a = fmaf(wp[3 * 32 + i], P1, a);
        a = fmaf(wp[4 * 32 + i], C1, a);
        a = fmaf(wp[5 * 32 + i], N1, a);
        a = fmaf(wp[6 * 32 + i], P2, a);
        a = fmaf(wp[7 * 32 + i], C2, a);
        a = fmaf(wp[8 * 32 + i], N2, a);
        swo[head][lane][i] = a;
        P0 = C0; C0 = N0;
        P1 = C1; C1 = N1;
        P2 = C2; C2 = N2;
    }
    __syncwarp();

    // Store pass: warp writes its 32 channels' rows coalesced
#pragma unroll 4
    for (int cc = 0; cc < 32; cc++) {
        const int gc = head * 32 + cc;
        out[(size_t)gc * NPIX + r1 + w0 + lane] = swo[head][cc][lane];
    }
}

// ---------------------------------------------------------------------------
extern "C" void kernel_launch(void* const* d_in, const int* in_sizes, int n_in,
                              void* d_out, int out_size)
{
    const float* x  = (const float*)d_in[0];
    const float* wq = (const float*)d_in[1];
    const float* wk = (const float*)d_in[2];
    const float* wv = (const float*)d_in[3];
    float* out = (float*)d_out;

    cudaFuncSetAttribute(qkv_mma_kernel,
                         cudaFuncAttributeMaxDynamicSharedMemorySize, SMEM_GEMM);

    wbf_kernel<<<768, 128>>>(wq, wk, wv);
    xt_kernel<<<dim3(NPIX / 32, 4), 256>>>(x);
    qkv_mma_kernel<<<dim3(288, 6), 256, SMEM_GEMM>>>();
    attn_kernel<<<dim3(WW / 32, HH), 256>>>(out);
}

// round 10
// speedup vs baseline: 1.6041x; 1.0326x over previous
#include <cuda_runtime.h>
#include <cuda_bf16.h>
#include <cstdint>

#define HH 192
#define WW 192
#define NPIX (HH * WW)      // 36864
#define CIN 128
#define NHEAD 8
#define KST 256             // [hi(128) | lo(128)] storage; 3 split terms via k remap

// Scratch
__device__ float g_vt[NPIX * 256];           // v projection, PIXEL-major [p][c]
__device__ float g_s0[NHEAD * NPIX];         // per-head q.k / 16
__device__ __nv_bfloat16 g_wbf[768 * KST];   // rows 0-511: per-head [q(32)|k(32)]; 512-767: v
__device__ __nv_bfloat16 g_xt[NPIX * KST];   // x transposed, [p][hi|lo]

// ---------------------------------------------------------------------------
// Helpers (base compute_103 features only: cp.async, ldmatrix, mma.sync)
// ---------------------------------------------------------------------------
__device__ __forceinline__ uint32_t smem_u32(const void* p) {
    uint32_t a;
    asm("{ .reg .u64 t; cvta.to.shared.u64 t, %1; cvt.u32.u64 %0, t; }" : "=r"(a) : "l"(p));
    return a;
}
__device__ __forceinline__ void cp16(uint32_t saddr, const void* g) {
    asm volatile("cp.async.cg.shared.global [%0], [%1], 16;\n" :: "r"(saddr), "l"(g));
}
__device__ __forceinline__ void ldsm_x4(uint32_t* r, uint32_t addr) {
    asm volatile("ldmatrix.sync.aligned.m8n8.x4.shared.b16 {%0,%1,%2,%3}, [%4];"
                 : "=r"(r[0]), "=r"(r[1]), "=r"(r[2]), "=r"(r[3]) : "r"(addr));
}
__device__ __forceinline__ void mma16816(float* d, const uint32_t* a, const uint32_t* b) {
    asm volatile(
        "mma.sync.aligned.m16n8k16.row.col.f32.bf16.bf16.f32 "
        "{%0,%1,%2,%3}, {%4,%5,%6,%7}, {%8,%9}, {%0,%1,%2,%3};"
        : "+f"(d[0]), "+f"(d[1]), "+f"(d[2]), "+f"(d[3])
        : "r"(a[0]), "r"(a[1]), "r"(a[2]), "r"(a[3]), "r"(b[0]), "r"(b[1]));
}

// Split-term k offsets per 32-wide K chunk kt in [0,12):
//   kt 0-3: hi.hi   kt 4-7: lo.hi   kt 8-11: hi.lo
__device__ __forceinline__ int kOffA(int kt) {
    return (kt < 4) ? kt * 32 : (kt < 8) ? 128 + (kt - 4) * 32 : (kt - 8) * 32;
}
__device__ __forceinline__ int kOffB(int kt) {
    return (kt < 4) ? kt * 32 : (kt < 8) ? (kt - 4) * 32 : 128 + (kt - 8) * 32;
}

// ---------------------------------------------------------------------------
// Precompute 1: split weights -> g_wbf [768][256] = [hi | lo]
// ---------------------------------------------------------------------------
__global__ void __launch_bounds__(128) wbf_kernel(
    const float* __restrict__ wq, const float* __restrict__ wk,
    const float* __restrict__ wv)
{
    const int r = blockIdx.x, c = threadIdx.x;
    const float* src;
    if (r < 512) {
        const int h = r >> 6, j = r & 63;
        src = (j < 32) ? wq + (h * 32 + j) * CIN
                       : wk + (h * 32 + j - 32) * CIN;
    } else {
        src = wv + (r - 512) * CIN;
    }
    const float a = src[c];
    const __nv_bfloat16 hi = __float2bfloat16(a);
    const __nv_bfloat16 lo = __float2bfloat16(a - __bfloat162float(hi));
    g_wbf[r * KST + c]       = hi;
    g_wbf[r * KST + 128 + c] = lo;
}

// ---------------------------------------------------------------------------
// Precompute 2: transpose + split x -> g_xt [36864][256] = [hi | lo]
// ---------------------------------------------------------------------------
__global__ void __launch_bounds__(256) xt_kernel(const float* __restrict__ x)
{
    __shared__ float tile[32][33];
    const int tx = threadIdx.x & 31, ty = threadIdx.x >> 5;
    const int p0 = blockIdx.x * 32, c0 = blockIdx.y * 32;
#pragma unroll
    for (int d = 0; d < 4; d++)
        tile[ty * 4 + d][tx] = x[(c0 + ty * 4 + d) * NPIX + p0 + tx];
    __syncthreads();
#pragma unroll
    for (int d = 0; d < 4; d++) {
        const int p = p0 + ty * 4 + d;
        const float a = tile[tx][ty * 4 + d];
        const __nv_bfloat16 hi = __float2bfloat16(a);
        const __nv_bfloat16 lo = __float2bfloat16(a - __bfloat162float(hi));
        g_xt[(size_t)p * KST + c0 + tx]       = hi;
        g_xt[(size_t)p * KST + 128 + c0 + tx] = lo;
    }
}

// ---------------------------------------------------------------------------
// Kernel A: HMMA GEMM, CTA 128x128, BK=32, 3-stage cp.async, 8 warps (2m x 4n).
// by 0-3: q/k tiles -> fused s0 epilogue. by 4-5: v tiles -> g_vt (pixel-major).
// One barrier per K-chunk: copies into stage (kt+2)%3 == (kt-1)%3 are issued
// right after the barrier, at which point all threads finished reading kt-1.
// ---------------------------------------------------------------------------
#define ASTRB 80
#define STG_BYTES (128 * ASTRB)
#define SMEM_GEMM (6 * STG_BYTES)     // 61440 B

__global__ void __launch_bounds__(256, 2) qkv_mma_kernel()
{
    extern __shared__ __align__(128) char smem[];
    const uint32_t sbase = smem_u32(smem);
    const int t = threadIdx.x, lane = t & 31, w = t >> 5;
    const int wm = w >> 2, wn = w & 3;
    const int by = blockIdx.y;
    const int m0 = by * 128;
    const int n0 = blockIdx.x * 128;

    const __nv_bfloat16* Ag = g_wbf + (size_t)m0 * KST;
    const __nv_bfloat16* Bg = g_xt  + (size_t)n0 * KST;

    const int r0c = t >> 2, c0c = t & 3;
    const int r1c = r0c + 64;

    auto issue_copy = [&](int kt) {
        const int s = kt % 3;
        const int ka = kOffA(kt), kb = kOffB(kt);
        const uint32_t sA = sbase + s * STG_BYTES;
        const uint32_t sB = sbase + 3 * STG_BYTES + s * STG_BYTES;
        cp16(sA + r0c * ASTRB + c0c * 16, Ag + (size_t)r0c * KST + ka + c0c * 8);
        cp16(sB + r0c * ASTRB + c0c * 16, Bg + (size_t)r0c * KST + kb + c0c * 8);
        cp16(sA + r1c * ASTRB + c0c * 16, Ag + (size_t)r1c * KST + ka + c0c * 8);
        cp16(sB + r1c * ASTRB + c0c * 16, Bg + (size_t)r1c * KST + kb + c0c * 8);
        asm volatile("cp.async.commit_group;\n");
    };

    issue_copy(0);
    issue_copy(1);

    float acc[4][4][4];
#pragma unroll
    for (int i = 0; i < 4; i++)
#pragma unroll
        for (int j = 0; j < 4; j++)
#pragma unroll
            for (int e = 0; e < 4; e++) acc[i][j][e] = 0.f;

    const uint32_t aRow = (uint32_t)(wm * 64 + (lane & 15));
    const uint32_t aChunkLane = (uint32_t)(lane >> 4);
    const int bsel = lane >> 3, br = lane & 7;
    const uint32_t bRowBase = (uint32_t)(wn * 32 + ((bsel >> 1) << 3) + br);
    const uint32_t bChunkLane = (uint32_t)(bsel & 1);

#pragma unroll 1
    for (int kt = 0; kt < 12; kt++) {
        if (kt < 11) asm volatile("cp.async.wait_group 1;\n" ::: "memory");
        else         asm volatile("cp.async.wait_group 0;\n" ::: "memory");
        __syncthreads();
        if (kt + 2 < 12) issue_copy(kt + 2);

        const int s = kt % 3;
        const uint32_t sA = sbase + s * STG_BYTES;
        const uint32_t sB = sbase + 3 * STG_BYTES + s * STG_BYTES;

#pragma unroll
        for (int ks = 0; ks < 2; ks++) {
            uint32_t afr[4][4];
#pragma unroll
            for (int mi = 0; mi < 4; mi++)
                ldsm_x4(afr[mi], sA + (aRow + mi * 16) * ASTRB
                                    + (ks * 2 + aChunkLane) * 16);
            uint32_t bfr[4][2];
#pragma unroll
            for (int ni2 = 0; ni2 < 2; ni2++) {
                uint32_t rr[4];
                ldsm_x4(rr, sB + (bRowBase + ni2 * 16) * ASTRB
                               + (ks * 2 + bChunkLane) * 16);
                bfr[ni2 * 2 + 0][0] = rr[0]; bfr[ni2 * 2 + 0][1] = rr[1];
                bfr[ni2 * 2 + 1][0] = rr[2]; bfr[ni2 * 2 + 1][1] = rr[3];
            }
#pragma unroll
            for (int mi = 0; mi < 4; mi++)
#pragma unroll
                for (int nj = 0; nj < 4; nj++)
                    mma16816(acc[mi][nj], afr[mi], bfr[nj]);
        }
    }

    if (by < 4) {
        const int head = 2 * by + wm;
        float part[4][2];
#pragma unroll
        for (int nj = 0; nj < 4; nj++)
#pragma unroll
            for (int pe = 0; pe < 2; pe++)
                part[nj][pe] = acc[0][nj][pe]     * acc[2][nj][pe]
                             + acc[1][nj][pe]     * acc[3][nj][pe]
                             + acc[0][nj][pe + 2] * acc[2][nj][pe + 2]
                             + acc[1][nj][pe + 2] * acc[3][nj][pe + 2];
#pragma unroll
        for (int d = 4; d <= 16; d <<= 1)
#pragma unroll
            for (int nj = 0; nj < 4; nj++)
#pragma unroll
                for (int pe = 0; pe < 2; pe++)
                    part[nj][pe] += __shfl_xor_sync(0xffffffffu, part[nj][pe], d);
        if ((lane >> 2) == 0) {
            float* dst = g_s0 + (size_t)head * NPIX + n0 + wn * 32 + (lane & 3) * 2;
#pragma unroll
            for (int nj = 0; nj < 4; nj++) {
                dst[nj * 8]     = part[nj][0] * 0.0625f;
                dst[nj * 8 + 1] = part[nj][1] * 0.0625f;
            }
        }
    } else {
        // v epilogue: transposed (pixel-major) scatter stores into g_vt[p][c]
        const int cBase = (by - 4) * 128 + wm * 64 + (lane >> 2);
        const int pBase = n0 + wn * 32 + (lane & 3) * 2;
#pragma unroll
        for (int mi = 0; mi < 4; mi++) {
#pragma unroll
            for (int nj = 0; nj < 4; nj++) {
                const int cc = cBase + mi * 16;
                const int pp = pBase + nj * 8;
                g_vt[(size_t)pp * 256 + cc]           = acc[mi][nj][0];
                g_vt[(size_t)(pp + 1) * 256 + cc]     = acc[mi][nj][1];
                g_vt[(size_t)pp * 256 + cc + 8]       = acc[mi][nj][2];
                g_vt[(size_t)(pp + 1) * 256 + cc + 8] = acc[mi][nj][3];
            }
        }
    }
}

// ---------------------------------------------------------------------------
// Kernel C: softmax over 9 shifted s0 (OOB slot -> logit 0 in softmax, weight
// 0 on the value product), then sliding-window 9-tap combine on pixel-major v.
// Phase 2: thread = 2 adjacent channels x 16 pixels, float2 loads.
// ---------------------------------------------------------------------------
__global__ void __launch_bounds__(256) attn_kernel(float* __restrict__ out)
{
    __shared__ float wsm[NHEAD * 9 * 32];      // [head][slot][pix], OOB -> 0
    __shared__ float swo[256][33];             // [channel][pix] out transpose
    const int t = threadIdx.x;
    const int h = blockIdx.y;
    const int w0 = blockIdx.x * 32;
    const int lane = t & 31;

    // Phase 1: softmax weights; warp = head, lane = pixel
    {
        const int head = t >> 5;
        const int w = w0 + lane;
        float lg[9];
        bool okm[9];
#pragma unroll
        for (int s = 0; s < 9; s++) {
            const int hh = h + s / 3 - 1;
            const int ww = w + s % 3 - 1;
            okm[s] = ((unsigned)hh < HH) && ((unsigned)ww < WW);
            lg[s] = okm[s] ? g_s0[head * NPIX + hh * WW + ww] : 0.0f;
        }
        float mx = lg[0];
#pragma unroll
        for (int s = 1; s < 9; s++) mx = fmaxf(mx, lg[s]);
        float e[9], sum = 0.f;
#pragma unroll
        for (int s = 0; s < 9; s++) { e[s] = __expf(lg[s] - mx); sum += e[s]; }
        const float inv = 1.0f / sum;
#pragma unroll
        for (int s = 0; s < 9; s++)
            wsm[(head * 9 + s) * 32 + lane] = okm[s] ? e[s] * inv : 0.0f;
    }
    __syncthreads();

    // Phase 2: thread -> channels {2*cg, 2*cg+1}, pixels [16*pg, 16*pg+16)
    {
        const int cg = t & 127, pg = t >> 7;
        const int c = 2 * cg;
        const int head = cg >> 4;
        const int r0 = max(h - 1, 0) * WW;
        const int r1 = h * WW;
        const int r2 = min(h + 1, HH - 1) * WW;
        const float* wp = &wsm[head * 9 * 32 + 16 * pg];
        const int wstart = w0 + 16 * pg;
        const int wl = max(wstart - 1, 0);

        const float* vt = g_vt + c;
        float2 P0 = *(const float2*)(vt + (size_t)(r0 + wl) * 256);
        float2 P1 = *(const float2*)(vt + (size_t)(r1 + wl) * 256);
        float2 P2 = *(const float2*)(vt + (size_t)(r2 + wl) * 256);
        float2 C0 = *(const float2*)(vt + (size_t)(r0 + wstart) * 256);
        float2 C1 = *(const float2*)(vt + (size_t)(r1 + wstart) * 256);
        float2 C2 = *(const float2*)(vt + (size_t)(r2 + wstart) * 256);

#pragma unroll 4
        for (int i = 0; i < 16; i++) {
            const int wn_ = min(wstart + i + 1, WW - 1);
            const float2 N0 = *(const float2*)(vt + (size_t)(r0 + wn_) * 256);
            const float2 N1 = *(const float2*)(vt + (size_t)(r1 + wn_) * 256);
            const float2 N2 = *(const float2*)(vt + (size_t)(r2 + wn_) * 256);
            const float w0_ = wp[0 * 32 + i], w1_ = wp[1 * 32 + i], w2_ = wp[2 * 32 + i];
            const float w3_ = wp[3 * 32 + i], w4_ = wp[4 * 32 + i], w5_ = wp[5 * 32 + i];
            const float w6_ = wp[6 * 32 + i], w7_ = wp[7 * 32 + i], w8_ = wp[8 * 32 + i];
            float ax = w0_ * P0.x, ay = w0_ * P0.y;
            ax = fmaf(w1_, C0.x, ax); ay = fmaf(w1_, C0.y, ay);
            ax = fmaf(w2_, N0.x, ax); ay = fmaf(w2_, N0.y, ay);
            ax = fmaf(w3_, P1.x, ax); ay = fmaf(w3_, P1.y, ay);
            ax = fmaf(w4_, C1.x, ax); ay = fmaf(w4_, C1.y, ay);
            ax = fmaf(w5_, N1.x, ax); ay = fmaf(w5_, N1.y, ay);
            ax = fmaf(w6_, P2.x, ax); ay = fmaf(w6_, P2.y, ay);
            ax = fmaf(w7_, C2.x, ax); ay = fmaf(w7_, C2.y, ay);
            ax = fmaf(w8_, N2.x, ax); ay = fmaf(w8_, N2.y, ay);
            swo[c][16 * pg + i]     = ax;
            swo[c + 1][16 * pg + i] = ay;
            P0 = C0; C0 = N0;
            P1 = C1; C1 = N1;
            P2 = C2; C2 = N2;
        }
    }
    __syncthreads();

    // Phase 3: warp = head, coalesced channel-major stores
    {
        const int head = t >> 5;
        const int r1 = h * WW;
#pragma unroll 4
        for (int cc = 0; cc < 32; cc++) {
            const int gc = head * 32 + cc;
            out[(size_t)gc * NPIX + r1 + w0 + lane] = swo[gc][lane];
        }
    }
}

// ---------------------------------------------------------------------------
extern "C" void kernel_launch(void* const* d_in, const int* in_sizes, int n_in,
                              void* d_out, int out_size)
{
    const float* x  = (const float*)d_in[0];
    const float* wq = (const float*)d_in[1];
    const float* wk = (const float*)d_in[2];
    const float* wv = (const float*)d_in[3];
    float* out = (float*)d_out;

    cudaFuncSetAttribute(qkv_mma_kernel,
                         cudaFuncAttributeMaxDynamicSharedMemorySize, SMEM_GEMM);

    wbf_kernel<<<768, 128>>>(wq, wk, wv);
    xt_kernel<<<dim3(NPIX / 32, 4), 256>>>(x);
    qkv_mma_kernel<<<dim3(288, 6), 256, SMEM_GEMM>>>();
    attn_kernel<<<dim3(WW / 32, HH), 256>>>(out);
}